// round 15
// baseline (speedup 1.0000x reference)
#include <cuda_runtime.h>
#include <cuda_fp16.h>
#include <cstdint>

#define N_NODES 50000
#define N_EDGES 800000
#define D_IN    128
#define D_HID   256
#define D_OUT   256

__device__ int g_is64;
__device__ int g_hist[N_NODES];
__device__ int g_off[N_NODES + 1];
__device__ int g_cursor[N_NODES];
__device__ int g_bsum[64];
__device__ int g_csr[N_EDGES];

#define F16ARR __device__ __align__(16) __half
F16ARR g_x16 [(size_t)N_NODES * D_IN];
F16ARR g_a116[(size_t)N_NODES * D_IN];
F16ARR g_h16 [(size_t)N_NODES * D_HID];
F16ARR g_a216[(size_t)N_NODES * D_HID];
F16ARR g_wl1[D_HID * D_IN];
F16ARR g_wr1[D_HID * D_IN];
F16ARR g_wl2[D_OUT * D_HID];
F16ARR g_wr2[D_OUT * D_HID];

__device__ __forceinline__ uint32_t smem_to_u32(const void* p) {
    uint32_t a;
    asm("{ .reg .u64 t; cvta.to.shared.u64 t, %1; cvt.u32.u64 %0, t; }" : "=r"(a) : "l"(p));
    return a;
}
__device__ __forceinline__ void cp_async16(uint32_t dst, const void* src, bool valid) {
    int sz = valid ? 16 : 0;
    asm volatile("cp.async.cg.shared.global [%0], [%1], 16, %2;"
                 :: "r"(dst), "l"(src), "r"(sz) : "memory");
}
__device__ __forceinline__ void cp_commit() {
    asm volatile("cp.async.commit_group;" ::: "memory");
}
__device__ __forceinline__ void ldsm_x4(uint32_t* r, uint32_t addr) {
    asm volatile("ldmatrix.sync.aligned.m8n8.x4.shared.b16 {%0,%1,%2,%3}, [%4];"
                 : "=r"(r[0]), "=r"(r[1]), "=r"(r[2]), "=r"(r[3]) : "r"(addr));
}
__device__ __forceinline__ void mma16816(float* d, const uint32_t* a,
                                         uint32_t b0, uint32_t b1) {
    asm volatile("mma.sync.aligned.m16n8k16.row.col.f32.f16.f16.f32 "
                 "{%0,%1,%2,%3}, {%4,%5,%6,%7}, {%8,%9}, {%0,%1,%2,%3};"
                 : "+f"(d[0]), "+f"(d[1]), "+f"(d[2]), "+f"(d[3])
                 : "r"(a[0]), "r"(a[1]), "r"(a[2]), "r"(a[3]), "r"(b0), "r"(b1));
}
__device__ __forceinline__ int load_idx(const void* base, int i) {
    if (g_is64) return (int)((const long long*)base)[i];
    return ((const int*)base)[i];
}

// ---------------------------------------------------------------------------
// Detect + hist-zero kernel: 49 blocks zero g_hist; block 0 also detects
// whether edge_index is int64 or int32.
// ---------------------------------------------------------------------------
#define N4_HZ ((N_NODES + 3) / 4)   // 12500 int4 zeros
__global__ void detect_zero_kernel(const long long* __restrict__ ei_ll, int* hist) {
    if (blockIdx.x == 0) {
        __shared__ int bad;
        if (threadIdx.x == 0) bad = 0;
        __syncthreads();
        for (int i = threadIdx.x; i < 4096; i += blockDim.x) {
            long long v = ei_ll[i];
            if (v < 0 || v >= N_NODES) bad = 1;
        }
        __syncthreads();
        if (threadIdx.x == 0) g_is64 = bad ? 0 : 1;
    }
    int i = blockIdx.x * blockDim.x + threadIdx.x;
    if (i < N4_HZ) ((int4*)hist)[i] = make_int4(0, 0, 0, 0);
}

// ---------------------------------------------------------------------------
// Prep + hist mega-kernel: grid-stride index space covers
// [x->fp16 | 4 weights->fp16 | edge histogram].  Per-range code identical
// to the previously separate kernels (no access-pattern change).
// Requires g_is64 set and hist zeroed (detect_zero_kernel runs first).
// ---------------------------------------------------------------------------
#define N4_X   (N_NODES * D_IN / 4)
#define N4_W1  (D_HID * D_IN / 4)
#define N4_W2  (D_OUT * D_HID / 4)
#define PREP_TOTAL (N4_X + 2 * N4_W1 + 2 * N4_W2 + N_EDGES)

__device__ __forceinline__ uint2 to_h4(float4 v) {
    __half2 p0 = __floats2half2_rn(v.x, v.y);
    __half2 p1 = __floats2half2_rn(v.z, v.w);
    return make_uint2(*(uint32_t*)&p0, *(uint32_t*)&p1);
}
__global__ void prep_hist_kernel(const void* __restrict__ ei,
                                 const float* x,
                                 const float* wl1, const float* wr1,
                                 const float* wl2, const float* wr2,
                                 __half* x16, __half* wl1h, __half* wr1h,
                                 __half* wl2h, __half* wr2h,
                                 int* __restrict__ hist) {
    int i = blockIdx.x * blockDim.x + threadIdx.x;
    int j = i;
    const float* src; __half* dst;
    if (j < N4_X)                      { src = x;   dst = x16; }
    else if ((j -= N4_X)   < N4_W1)    { src = wl1; dst = wl1h; }
    else if ((j -= N4_W1)  < N4_W1)    { src = wr1; dst = wr1h; }
    else if ((j -= N4_W1)  < N4_W2)    { src = wl2; dst = wl2h; }
    else if ((j -= N4_W2)  < N4_W2)    { src = wr2; dst = wr2h; }
    else {
        j -= N4_W2;
        if (j < N_EDGES) atomicAdd(&hist[load_idx(ei, N_EDGES + j)], 1);
        return;
    }
    ((uint2*)dst)[j] = to_h4(((const float4*)src)[j]);
}

// ---------------------------------------------------------------------------
// Scan (2 kernels): per-block scan + block sums, then scan3 which also
// (redundantly per block) prefix-scans the 49 block sums in shared memory.
// ---------------------------------------------------------------------------
#define SCAN_NB ((N_NODES + 1023) / 1024)   // 49
__global__ void scan1_kernel(const int* __restrict__ hist,
                             int* __restrict__ off, int* __restrict__ bsum) {
    __shared__ int sh[1024];
    int gid = blockIdx.x * 1024 + threadIdx.x;
    int v = (gid < N_NODES) ? hist[gid] : 0;
    sh[threadIdx.x] = v;
    __syncthreads();
    for (int o = 1; o < 1024; o <<= 1) {
        int t = (threadIdx.x >= o) ? sh[threadIdx.x - o] : 0;
        __syncthreads();
        sh[threadIdx.x] += t;
        __syncthreads();
    }
    if (gid < N_NODES) off[gid] = sh[threadIdx.x] - v;
    if (threadIdx.x == 1023) bsum[blockIdx.x] = sh[1023];
}
__global__ void scan3_kernel(int* __restrict__ off, const int* __restrict__ bsum,
                             int* __restrict__ cursor) {
    __shared__ int sb[64];
    const int t = threadIdx.x;
    if (t < 64) sb[t] = (t < SCAN_NB) ? bsum[t] : 0;
    __syncthreads();
#pragma unroll
    for (int o = 1; o < 64; o <<= 1) {
        int u = (t >= o && t < 64) ? sb[t - o] : 0;
        __syncthreads();
        if (t < 64) sb[t] += u;
        __syncthreads();
    }
    // sb is now inclusive prefix; base for segment k = sb[k-1] (0 for k=0)
    int gid = blockIdx.x * blockDim.x + t;
    if (gid < N_NODES) {
        int seg = gid >> 10;
        int base = seg ? sb[seg - 1] : 0;
        int v = off[gid] + base;
        off[gid] = v;
        cursor[gid] = v;
    }
    if (gid == 0) off[N_NODES] = N_EDGES;
}
__global__ void fill_kernel(const void* __restrict__ ei,
                            int* __restrict__ cursor, int* __restrict__ csr) {
    int e = blockIdx.x * blockDim.x + threadIdx.x;
    if (e >= N_EDGES) return;
    int s = load_idx(ei, e);
    int d = load_idx(ei, N_EDGES + e);
    csr[atomicAdd(&cursor[d], 1)] = s;
}

// ---------------------------------------------------------------------------
// CSR mean aggregation (round-8/10, unchanged)
// ---------------------------------------------------------------------------
template<int D>
__global__ void agg_kernel(const __half* __restrict__ feat,
                           const int* __restrict__ off,
                           const int* __restrict__ csr,
                           __half* __restrict__ out) {
    int warp = (blockIdx.x * blockDim.x + threadIdx.x) >> 5;
    int lane = threadIdx.x & 31;
    if (warp >= N_NODES) return;
    const int beg = off[warp], end = off[warp + 1];
    constexpr int H  = D / 32;
    constexpr int H2 = H / 2;

    float acc[H];
#pragma unroll
    for (int i = 0; i < H; i++) acc[i] = 0.f;

    int j = beg;
    for (; j + 1 < end; j += 2) {
        int s0 = csr[j], s1 = csr[j + 1];
        uint32_t v0[H2], v1[H2];
        if (H2 == 2) {
            uint2 t0 = *(const uint2*)(feat + (size_t)s0 * D + lane * H);
            uint2 t1 = *(const uint2*)(feat + (size_t)s1 * D + lane * H);
            v0[0] = t0.x; v0[1] = t0.y; v1[0] = t1.x; v1[1] = t1.y;
        } else {
            uint4 t0 = *(const uint4*)(feat + (size_t)s0 * D + lane * H);
            uint4 t1 = *(const uint4*)(feat + (size_t)s1 * D + lane * H);
            v0[0] = t0.x; v0[1] = t0.y; v0[2] = t0.z; v0[3] = t0.w;
            v1[0] = t1.x; v1[1] = t1.y; v1[2] = t1.z; v1[3] = t1.w;
        }
#pragma unroll
        for (int i = 0; i < H2; i++) {
            float2 f0 = __half22float2(*(const __half2*)&v0[i]);
            float2 f1 = __half22float2(*(const __half2*)&v1[i]);
            acc[2*i]   += f0.x + f1.x;
            acc[2*i+1] += f0.y + f1.y;
        }
    }
    if (j < end) {
        int s0 = csr[j];
        uint32_t v0[H2];
        if (H2 == 2) {
            uint2 t0 = *(const uint2*)(feat + (size_t)s0 * D + lane * H);
            v0[0] = t0.x; v0[1] = t0.y;
        } else {
            uint4 t0 = *(const uint4*)(feat + (size_t)s0 * D + lane * H);
            v0[0] = t0.x; v0[1] = t0.y; v0[2] = t0.z; v0[3] = t0.w;
        }
#pragma unroll
        for (int i = 0; i < H2; i++) {
            float2 f0 = __half22float2(*(const __half2*)&v0[i]);
            acc[2*i] += f0.x; acc[2*i+1] += f0.y;
        }
    }

    float inv = 1.f / fmaxf((float)(end - beg), 1.f);
    uint32_t w[H2];
#pragma unroll
    for (int i = 0; i < H2; i++) {
        __half2 r = __floats2half2_rn(acc[2*i] * inv, acc[2*i+1] * inv);
        w[i] = *(uint32_t*)&r;
    }
    __half* op = out + (size_t)warp * D + lane * H;
    if (H2 == 2) *(uint2*)op = make_uint2(w[0], w[1]);
    else         *(uint4*)op = make_uint4(w[0], w[1], w[2], w[3]);
}

// ---------------------------------------------------------------------------
// Single-pass fp16 fused GEMM, 3-stage cp.async ring (round-8/10, unchanged)
// ---------------------------------------------------------------------------
#define PITCH 144
#define TILE_BYTES (128 * PITCH)
#define STAGE_BYTES (2 * TILE_BYTES)
#define GEMM_SMEM (3 * STAGE_BYTES)

template<int K1, bool F16OUT>
__global__ __launch_bounds__(256, 2)
void gemm1p_kernel(const __half* __restrict__ A1, const __half* __restrict__ A2,
                   const __half* __restrict__ B1, const __half* __restrict__ B2,
                   const float* __restrict__ bias, float* __restrict__ C,
                   __half* __restrict__ H, int M) {
    extern __shared__ char smem[];
    constexpr int NCH = K1 / 64;
    constexpr int CT  = 2 * NCH;

    const uint32_t smem_base = smem_to_u32(smem);
    const int tid = threadIdx.x;
    const int wid = tid >> 5, lane = tid & 31;
    const int wm = wid & 3, wn = wid >> 2;
    const int m0  = blockIdx.x * 128;
    const int bn0 = blockIdx.y * 128;

    float acc[2][8][4];
#pragma unroll
    for (int i = 0; i < 2; i++)
#pragma unroll
        for (int j = 0; j < 8; j++)
#pragma unroll
            for (int r = 0; r < 4; r++) acc[i][j][r] = 0.f;

    auto issue = [&](int c, int stg) {
        const int mtx = c / NCH;
        const int k0 = (c % NCH) * 64;
        const __half* Ap = mtx ? A2 : A1;
        const __half* Bp = mtx ? B2 : B1;
        const uint32_t s0 = smem_base + stg * STAGE_BYTES;
#pragma unroll
        for (int it = 0; it < 4; it++) {
            int idx = tid + it * 256;
            int row = idx >> 3, ch = idx & 7;
            int gm = m0 + row;
            cp_async16(s0 + row * PITCH + ch * 16,
                       Ap + (size_t)gm * K1 + k0 + ch * 8, gm < M);
            cp_async16(s0 + TILE_BYTES + row * PITCH + ch * 16,
                       Bp + (size_t)(bn0 + row) * K1 + k0 + ch * 8, true);
        }
        cp_commit();
    };

    issue(0, 0);
    if (CT > 1) issue(1, 1);

    const int arow = wm * 32 + (lane & 15);
    const int brow = wn * 64 + (lane & 15);
    const int chi  = lane >> 4;

    for (int c = 0; c < CT; c++) {
        const int s = c % 3;
        if (c + 2 < CT) issue(c + 2, (c + 2) % 3);

        if (c + 2 < CT)      asm volatile("cp.async.wait_group 2;" ::: "memory");
        else if (c + 1 < CT) asm volatile("cp.async.wait_group 1;" ::: "memory");
        else                 asm volatile("cp.async.wait_group 0;" ::: "memory");
        __syncthreads();

        const uint32_t sa = smem_base + s * STAGE_BYTES;
        const uint32_t sb = sa + TILE_BYTES;
#pragma unroll
        for (int kk = 0; kk < 4; kk++) {
            uint32_t a[2][4], b[4][4];
#pragma unroll
            for (int am = 0; am < 2; am++)
                ldsm_x4(a[am], sa + (uint32_t)(arow + am * 16) * PITCH
                                  + (uint32_t)(kk * 2 + chi) * 16);
#pragma unroll
            for (int bi = 0; bi < 4; bi++)
                ldsm_x4(b[bi], sb + (uint32_t)(brow + bi * 16) * PITCH
                                  + (uint32_t)(kk * 2 + chi) * 16);
#pragma unroll
            for (int am = 0; am < 2; am++)
#pragma unroll
                for (int bi = 0; bi < 4; bi++) {
                    mma16816(acc[am][2 * bi + 0], a[am], b[bi][0], b[bi][2]);
                    mma16816(acc[am][2 * bi + 1], a[am], b[bi][1], b[bi][3]);
                }
        }
        __syncthreads();
    }

#pragma unroll
    for (int am = 0; am < 2; am++) {
        int gm = m0 + wm * 32 + am * 16 + (lane >> 2);
#pragma unroll
        for (int bi = 0; bi < 8; bi++) {
            int gn = bn0 + wn * 64 + bi * 8 + (lane & 3) * 2;
            float bz0 = bias[gn], bz1 = bias[gn + 1];
#pragma unroll
            for (int half = 0; half < 2; half++) {
                int r = gm + half * 8;
                if (r >= M) continue;
                float v0 = fmaxf(acc[am][bi][2 * half + 0] + bz0, 0.f);
                float v1 = fmaxf(acc[am][bi][2 * half + 1] + bz1, 0.f);
                if (F16OUT) {
                    __half2 p = __floats2half2_rn(v0, v1);
                    *(uint32_t*)(H + (size_t)r * 256 + gn) = *(uint32_t*)&p;
                } else {
                    *(float2*)(C + (size_t)r * 256 + gn) = make_float2(v0, v1);
                }
            }
        }
    }
}

// ---- Launch ----
extern "C" void kernel_launch(void* const* d_in, const int* in_sizes, int n_in,
                              void* d_out, int out_size) {
    const float* x    = (const float*)d_in[0];
    const void*  ei   = d_in[1];
    const float* w_l1 = (const float*)d_in[2];
    const float* b_l1 = (const float*)d_in[3];
    const float* w_r1 = (const float*)d_in[4];
    const float* w_l2 = (const float*)d_in[5];
    const float* b_l2 = (const float*)d_in[6];
    const float* w_r2 = (const float*)d_in[7];
    float* out = (float*)d_out;

    int *hist, *off, *cursor, *bsum, *csr;
    cudaGetSymbolAddress((void**)&hist,   g_hist);
    cudaGetSymbolAddress((void**)&off,    g_off);
    cudaGetSymbolAddress((void**)&cursor, g_cursor);
    cudaGetSymbolAddress((void**)&bsum,   g_bsum);
    cudaGetSymbolAddress((void**)&csr,    g_csr);
    __half *x16, *a116, *h16, *a216, *wl1, *wr1, *wl2, *wr2;
    cudaGetSymbolAddress((void**)&x16,  g_x16);
    cudaGetSymbolAddress((void**)&a116, g_a116);
    cudaGetSymbolAddress((void**)&h16,  g_h16);
    cudaGetSymbolAddress((void**)&a216, g_a216);
    cudaGetSymbolAddress((void**)&wl1,  g_wl1);
    cudaGetSymbolAddress((void**)&wr1,  g_wr1);
    cudaGetSymbolAddress((void**)&wl2,  g_wl2);
    cudaGetSymbolAddress((void**)&wr2,  g_wr2);

    cudaFuncSetAttribute(gemm1p_kernel<D_IN,  true >,
                         cudaFuncAttributeMaxDynamicSharedMemorySize, GEMM_SMEM);
    cudaFuncSetAttribute(gemm1p_kernel<D_HID, false>,
                         cudaFuncAttributeMaxDynamicSharedMemorySize, GEMM_SMEM);

    // CSR build + prep (8 launches total)
    detect_zero_kernel<<<(N4_HZ + 255) / 256, 256>>>((const long long*)ei, hist);
    prep_hist_kernel<<<(PREP_TOTAL + 255) / 256, 256>>>(
        ei, x, w_l1, w_r1, w_l2, w_r2, x16, wl1, wr1, wl2, wr2, hist);
    scan1_kernel<<<SCAN_NB, 1024>>>(hist, off, bsum);
    scan3_kernel<<<(N_NODES + 255) / 256, 256>>>(off, bsum, cursor);
    fill_kernel<<<(N_EDGES + 255) / 256, 256>>>(ei, cursor, csr);

    const dim3 gemm_grid((N_NODES + 127) / 128, 2);
    const int agg_blocks = (N_NODES * 32 + 255) / 256;

    // Layer 1
    agg_kernel<D_IN><<<agg_blocks, 256>>>(x16, off, csr, a116);
    gemm1p_kernel<D_IN, true><<<gemm_grid, 256, GEMM_SMEM>>>(
        a116, x16, wl1, wr1, b_l1, nullptr, h16, N_NODES);

    // Layer 2
    agg_kernel<D_HID><<<agg_blocks, 256>>>(h16, off, csr, a216);
    gemm1p_kernel<D_HID, false><<<gemm_grid, 256, GEMM_SMEM>>>(
        a216, h16, wl2, wr2, b_l2, out, nullptr, N_NODES);
}

// round 16
// speedup vs baseline: 1.0367x; 1.0367x over previous
#include <cuda_runtime.h>
#include <cuda_fp16.h>
#include <cstdint>

#define N_NODES 50000
#define N_EDGES 800000
#define D_IN    128
#define D_HID   256
#define D_OUT   256

__device__ int g_is64;
__device__ int g_hist[N_NODES];
__device__ int g_off[N_NODES + 1];
__device__ int g_cursor[N_NODES];
__device__ int g_bsum[64];
__device__ int g_csr[N_EDGES];

#define F16ARR __device__ __align__(16) __half
F16ARR g_x16 [(size_t)N_NODES * D_IN];
F16ARR g_a116[(size_t)N_NODES * D_IN];
F16ARR g_h16 [(size_t)N_NODES * D_HID];
F16ARR g_a216[(size_t)N_NODES * D_HID];
F16ARR g_wl1[D_HID * D_IN];
F16ARR g_wr1[D_HID * D_IN];
F16ARR g_wl2[D_OUT * D_HID];
F16ARR g_wr2[D_OUT * D_HID];

__device__ __forceinline__ uint32_t smem_to_u32(const void* p) {
    uint32_t a;
    asm("{ .reg .u64 t; cvta.to.shared.u64 t, %1; cvt.u32.u64 %0, t; }" : "=r"(a) : "l"(p));
    return a;
}
__device__ __forceinline__ void cp_async16(uint32_t dst, const void* src, bool valid) {
    int sz = valid ? 16 : 0;
    asm volatile("cp.async.cg.shared.global [%0], [%1], 16, %2;"
                 :: "r"(dst), "l"(src), "r"(sz) : "memory");
}
__device__ __forceinline__ void cp_commit() {
    asm volatile("cp.async.commit_group;" ::: "memory");
}
__device__ __forceinline__ void ldsm_x4(uint32_t* r, uint32_t addr) {
    asm volatile("ldmatrix.sync.aligned.m8n8.x4.shared.b16 {%0,%1,%2,%3}, [%4];"
                 : "=r"(r[0]), "=r"(r[1]), "=r"(r[2]), "=r"(r[3]) : "r"(addr));
}
__device__ __forceinline__ void mma16816(float* d, const uint32_t* a,
                                         uint32_t b0, uint32_t b1) {
    asm volatile("mma.sync.aligned.m16n8k16.row.col.f32.f16.f16.f32 "
                 "{%0,%1,%2,%3}, {%4,%5,%6,%7}, {%8,%9}, {%0,%1,%2,%3};"
                 : "+f"(d[0]), "+f"(d[1]), "+f"(d[2]), "+f"(d[3])
                 : "r"(a[0]), "r"(a[1]), "r"(a[2]), "r"(a[3]), "r"(b0), "r"(b1));
}
__device__ __forceinline__ int load_idx(const void* base, int i) {
    if (g_is64) return (int)((const long long*)base)[i];
    return ((const int*)base)[i];
}

// ---------------------------------------------------------------------------
// Prep mega-kernel: block 0 runs int64/int32 detection; all blocks cover
// [hist-zero | x->fp16 | 4 weights->fp16].  (round-10/14 version)
// ---------------------------------------------------------------------------
#define N4_HZ  (N_NODES / 4)
#define N4_X   (N_NODES * D_IN / 4)
#define N4_W1  (D_HID * D_IN / 4)
#define N4_W2  (D_OUT * D_HID / 4)
#define PREP_TOTAL (N4_HZ + N4_X + 2 * N4_W1 + 2 * N4_W2)

__device__ __forceinline__ uint2 to_h4(float4 v) {
    __half2 p0 = __floats2half2_rn(v.x, v.y);
    __half2 p1 = __floats2half2_rn(v.z, v.w);
    return make_uint2(*(uint32_t*)&p0, *(uint32_t*)&p1);
}
__global__ void prep_kernel(const long long* __restrict__ ei_ll,
                            const float* x,
                            const float* wl1, const float* wr1,
                            const float* wl2, const float* wr2,
                            __half* x16, __half* wl1h, __half* wr1h,
                            __half* wl2h, __half* wr2h, int* hist) {
    if (blockIdx.x == 0) {
        __shared__ int bad;
        if (threadIdx.x == 0) bad = 0;
        __syncthreads();
        for (int i = threadIdx.x; i < 4096; i += blockDim.x) {
            long long v = ei_ll[i];
            if (v < 0 || v >= N_NODES) bad = 1;
        }
        __syncthreads();
        if (threadIdx.x == 0) g_is64 = bad ? 0 : 1;
    }
    int i = blockIdx.x * blockDim.x + threadIdx.x;
    int j = i;
    if (j < N4_HZ) { ((int4*)hist)[j] = make_int4(0, 0, 0, 0); return; }
    j -= N4_HZ;
    const float* src; __half* dst;
    if (j < N4_X)                      { src = x;   dst = x16; }
    else if ((j -= N4_X)   < N4_W1)    { src = wl1; dst = wl1h; }
    else if ((j -= N4_W1)  < N4_W1)    { src = wr1; dst = wr1h; }
    else if ((j -= N4_W1)  < N4_W2)    { src = wl2; dst = wl2h; }
    else if ((j -= N4_W2)  < N4_W2)    { src = wr2; dst = wr2h; }
    else return;
    ((uint2*)dst)[j] = to_h4(((const float4*)src)[j]);
}

// ---------------------------------------------------------------------------
// CSR build (round-10/14: 1 edge/thread, 3-kernel coalesced scan,
// 64-thread scan2)
// ---------------------------------------------------------------------------
__global__ void hist_kernel(const void* __restrict__ ei, int* __restrict__ hist) {
    int e = blockIdx.x * blockDim.x + threadIdx.x;
    if (e >= N_EDGES) return;
    atomicAdd(&hist[load_idx(ei, N_EDGES + e)], 1);
}
#define SCAN_NB ((N_NODES + 1023) / 1024)   // 49
__global__ void scan1_kernel(const int* __restrict__ hist,
                             int* __restrict__ off, int* __restrict__ bsum) {
    __shared__ int sh[1024];
    int gid = blockIdx.x * 1024 + threadIdx.x;
    int v = (gid < N_NODES) ? hist[gid] : 0;
    sh[threadIdx.x] = v;
    __syncthreads();
    for (int o = 1; o < 1024; o <<= 1) {
        int t = (threadIdx.x >= o) ? sh[threadIdx.x - o] : 0;
        __syncthreads();
        sh[threadIdx.x] += t;
        __syncthreads();
    }
    if (gid < N_NODES) off[gid] = sh[threadIdx.x] - v;
    if (threadIdx.x == 1023) bsum[blockIdx.x] = sh[1023];
}
__global__ void scan2_kernel(int* bsum) {
    __shared__ int sb[64];
    int t = threadIdx.x;
    sb[t] = (t < SCAN_NB) ? bsum[t] : 0;
    __syncthreads();
#pragma unroll
    for (int o = 1; o < 64; o <<= 1) {
        int u = (t >= o) ? sb[t - o] : 0;
        __syncthreads();
        sb[t] += u;
        __syncthreads();
    }
    if (t < SCAN_NB) bsum[t] = (t > 0) ? sb[t - 1] : 0;
}
__global__ void scan3_kernel(int* __restrict__ off, const int* __restrict__ bsum,
                             int* __restrict__ cursor) {
    int gid = blockIdx.x * blockDim.x + threadIdx.x;
    if (gid < N_NODES) {
        int v = off[gid] + bsum[gid >> 10];
        off[gid] = v;
        cursor[gid] = v;
    }
    if (gid == 0) off[N_NODES] = N_EDGES;
}
__global__ void fill_kernel(const void* __restrict__ ei,
                            int* __restrict__ cursor, int* __restrict__ csr) {
    int e = blockIdx.x * blockDim.x + threadIdx.x;
    if (e >= N_EDGES) return;
    int s = load_idx(ei, e);
    int d = load_idx(ei, N_EDGES + e);
    csr[atomicAdd(&cursor[d], 1)] = s;
}

// ---------------------------------------------------------------------------
// CSR mean aggregation: one warp per node; 4-way independent row gathers
// (indices loaded directly from csr — same coalesced pattern, MLP 2 -> 4).
// fp32 register accumulate; fp16 mean out.
// ---------------------------------------------------------------------------
template<int D>
__global__ void agg_kernel(const __half* __restrict__ feat,
                           const int* __restrict__ off,
                           const int* __restrict__ csr,
                           __half* __restrict__ out) {
    int warp = (blockIdx.x * blockDim.x + threadIdx.x) >> 5;
    int lane = threadIdx.x & 31;
    if (warp >= N_NODES) return;
    const int beg = off[warp], end = off[warp + 1];
    constexpr int H  = D / 32;
    constexpr int H2 = H / 2;

    float acc[H];
#pragma unroll
    for (int i = 0; i < H; i++) acc[i] = 0.f;

    int j = beg;
    for (; j + 3 < end; j += 4) {
        int s0 = csr[j], s1 = csr[j + 1], s2 = csr[j + 2], s3 = csr[j + 3];
        if (H2 == 2) {
            uint2 t0 = *(const uint2*)(feat + (size_t)s0 * D + lane * H);
            uint2 t1 = *(const uint2*)(feat + (size_t)s1 * D + lane * H);
            uint2 t2 = *(const uint2*)(feat + (size_t)s2 * D + lane * H);
            uint2 t3 = *(const uint2*)(feat + (size_t)s3 * D + lane * H);
            uint32_t v[4][2] = {{t0.x, t0.y}, {t1.x, t1.y}, {t2.x, t2.y}, {t3.x, t3.y}};
#pragma unroll
            for (int r = 0; r < 4; r++)
#pragma unroll
                for (int i = 0; i < 2; i++) {
                    float2 f = __half22float2(*(const __half2*)&v[r][i]);
                    acc[2*i]   += f.x;
                    acc[2*i+1] += f.y;
                }
        } else {
            uint4 t0 = *(const uint4*)(feat + (size_t)s0 * D + lane * H);
            uint4 t1 = *(const uint4*)(feat + (size_t)s1 * D + lane * H);
            uint4 t2 = *(const uint4*)(feat + (size_t)s2 * D + lane * H);
            uint4 t3 = *(const uint4*)(feat + (size_t)s3 * D + lane * H);
            uint32_t v[4][4] = {{t0.x, t0.y, t0.z, t0.w}, {t1.x, t1.y, t1.z, t1.w},
                                {t2.x, t2.y, t2.z, t2.w}, {t3.x, t3.y, t3.z, t3.w}};
#pragma unroll
            for (int r = 0; r < 4; r++)
#pragma unroll
                for (int i = 0; i < 4; i++) {
                    float2 f = __half22float2(*(const __half2*)&v[r][i]);
                    acc[2*i]   += f.x;
                    acc[2*i+1] += f.y;
                }
        }
    }
    for (; j < end; j++) {
        int s0 = csr[j];
        if (H2 == 2) {
            uint2 t0 = *(const uint2*)(feat + (size_t)s0 * D + lane * H);
            uint32_t v[2] = {t0.x, t0.y};
#pragma unroll
            for (int i = 0; i < 2; i++) {
                float2 f = __half22float2(*(const __half2*)&v[i]);
                acc[2*i] += f.x; acc[2*i+1] += f.y;
            }
        } else {
            uint4 t0 = *(const uint4*)(feat + (size_t)s0 * D + lane * H);
            uint32_t v[4] = {t0.x, t0.y, t0.z, t0.w};
#pragma unroll
            for (int i = 0; i < 4; i++) {
                float2 f = __half22float2(*(const __half2*)&v[i]);
                acc[2*i] += f.x; acc[2*i+1] += f.y;
            }
        }
    }

    float inv = 1.f / fmaxf((float)(end - beg), 1.f);
    uint32_t w[H2];
#pragma unroll
    for (int i = 0; i < H2; i++) {
        __half2 r = __floats2half2_rn(acc[2*i] * inv, acc[2*i+1] * inv);
        w[i] = *(uint32_t*)&r;
    }
    __half* op = out + (size_t)warp * D + lane * H;
    if (H2 == 2) *(uint2*)op = make_uint2(w[0], w[1]);
    else         *(uint4*)op = make_uint4(w[0], w[1], w[2], w[3]);
}

// ---------------------------------------------------------------------------
// Single-pass fp16 fused GEMM, 3-stage cp.async ring (round-8/10, unchanged)
// ---------------------------------------------------------------------------
#define PITCH 144
#define TILE_BYTES (128 * PITCH)
#define STAGE_BYTES (2 * TILE_BYTES)
#define GEMM_SMEM (3 * STAGE_BYTES)

template<int K1, bool F16OUT>
__global__ __launch_bounds__(256, 2)
void gemm1p_kernel(const __half* __restrict__ A1, const __half* __restrict__ A2,
                   const __half* __restrict__ B1, const __half* __restrict__ B2,
                   const float* __restrict__ bias, float* __restrict__ C,
                   __half* __restrict__ H, int M) {
    extern __shared__ char smem[];
    constexpr int NCH = K1 / 64;
    constexpr int CT  = 2 * NCH;

    const uint32_t smem_base = smem_to_u32(smem);
    const int tid = threadIdx.x;
    const int wid = tid >> 5, lane = tid & 31;
    const int wm = wid & 3, wn = wid >> 2;
    const int m0  = blockIdx.x * 128;
    const int bn0 = blockIdx.y * 128;

    float acc[2][8][4];
#pragma unroll
    for (int i = 0; i < 2; i++)
#pragma unroll
        for (int j = 0; j < 8; j++)
#pragma unroll
            for (int r = 0; r < 4; r++) acc[i][j][r] = 0.f;

    auto issue = [&](int c, int stg) {
        const int mtx = c / NCH;
        const int k0 = (c % NCH) * 64;
        const __half* Ap = mtx ? A2 : A1;
        const __half* Bp = mtx ? B2 : B1;
        const uint32_t s0 = smem_base + stg * STAGE_BYTES;
#pragma unroll
        for (int it = 0; it < 4; it++) {
            int idx = tid + it * 256;
            int row = idx >> 3, ch = idx & 7;
            int gm = m0 + row;
            cp_async16(s0 + row * PITCH + ch * 16,
                       Ap + (size_t)gm * K1 + k0 + ch * 8, gm < M);
            cp_async16(s0 + TILE_BYTES + row * PITCH + ch * 16,
                       Bp + (size_t)(bn0 + row) * K1 + k0 + ch * 8, true);
        }
        cp_commit();
    };

    issue(0, 0);
    if (CT > 1) issue(1, 1);

    const int arow = wm * 32 + (lane & 15);
    const int brow = wn * 64 + (lane & 15);
    const int chi  = lane >> 4;

    for (int c = 0; c < CT; c++) {
        const int s = c % 3;
        if (c + 2 < CT) issue(c + 2, (c + 2) % 3);

        if (c + 2 < CT)      asm volatile("cp.async.wait_group 2;" ::: "memory");
        else if (c + 1 < CT) asm volatile("cp.async.wait_group 1;" ::: "memory");
        else                 asm volatile("cp.async.wait_group 0;" ::: "memory");
        __syncthreads();

        const uint32_t sa = smem_base + s * STAGE_BYTES;
        const uint32_t sb = sa + TILE_BYTES;
#pragma unroll
        for (int kk = 0; kk < 4; kk++) {
            uint32_t a[2][4], b[4][4];
#pragma unroll
            for (int am = 0; am < 2; am++)
                ldsm_x4(a[am], sa + (uint32_t)(arow + am * 16) * PITCH
                                  + (uint32_t)(kk * 2 + chi) * 16);
#pragma unroll
            for (int bi = 0; bi < 4; bi++)
                ldsm_x4(b[bi], sb + (uint32_t)(brow + bi * 16) * PITCH
                                  + (uint32_t)(kk * 2 + chi) * 16);
#pragma unroll
            for (int am = 0; am < 2; am++)
#pragma unroll
                for (int bi = 0; bi < 4; bi++) {
                    mma16816(acc[am][2 * bi + 0], a[am], b[bi][0], b[bi][2]);
                    mma16816(acc[am][2 * bi + 1], a[am], b[bi][1], b[bi][3]);
                }
        }
        __syncthreads();
    }

#pragma unroll
    for (int am = 0; am < 2; am++) {
        int gm = m0 + wm * 32 + am * 16 + (lane >> 2);
#pragma unroll
        for (int bi = 0; bi < 8; bi++) {
            int gn = bn0 + wn * 64 + bi * 8 + (lane & 3) * 2;
            float bz0 = bias[gn], bz1 = bias[gn + 1];
#pragma unroll
            for (int half = 0; half < 2; half++) {
                int r = gm + half * 8;
                if (r >= M) continue;
                float v0 = fmaxf(acc[am][bi][2 * half + 0] + bz0, 0.f);
                float v1 = fmaxf(acc[am][bi][2 * half + 1] + bz1, 0.f);
                if (F16OUT) {
                    __half2 p = __floats2half2_rn(v0, v1);
                    *(uint32_t*)(H + (size_t)r * 256 + gn) = *(uint32_t*)&p;
                } else {
                    *(float2*)(C + (size_t)r * 256 + gn) = make_float2(v0, v1);
                }
            }
        }
    }
}

// ---- Launch ----
extern "C" void kernel_launch(void* const* d_in, const int* in_sizes, int n_in,
                              void* d_out, int out_size) {
    const float* x    = (const float*)d_in[0];
    const void*  ei   = d_in[1];
    const float* w_l1 = (const float*)d_in[2];
    const float* b_l1 = (const float*)d_in[3];
    const float* w_r1 = (const float*)d_in[4];
    const float* w_l2 = (const float*)d_in[5];
    const float* b_l2 = (const float*)d_in[6];
    const float* w_r2 = (const float*)d_in[7];
    float* out = (float*)d_out;

    int *hist, *off, *cursor, *bsum, *csr;
    cudaGetSymbolAddress((void**)&hist,   g_hist);
    cudaGetSymbolAddress((void**)&off,    g_off);
    cudaGetSymbolAddress((void**)&cursor, g_cursor);
    cudaGetSymbolAddress((void**)&bsum,   g_bsum);
    cudaGetSymbolAddress((void**)&csr,    g_csr);
    __half *x16, *a116, *h16, *a216, *wl1, *wr1, *wl2, *wr2;
    cudaGetSymbolAddress((void**)&x16,  g_x16);
    cudaGetSymbolAddress((void**)&a116, g_a116);
    cudaGetSymbolAddress((void**)&h16,  g_h16);
    cudaGetSymbolAddress((void**)&a216, g_a216);
    cudaGetSymbolAddress((void**)&wl1,  g_wl1);
    cudaGetSymbolAddress((void**)&wr1,  g_wr1);
    cudaGetSymbolAddress((void**)&wl2,  g_wl2);
    cudaGetSymbolAddress((void**)&wr2,  g_wr2);

    cudaFuncSetAttribute(gemm1p_kernel<D_IN,  true >,
                         cudaFuncAttributeMaxDynamicSharedMemorySize, GEMM_SMEM);
    cudaFuncSetAttribute(gemm1p_kernel<D_HID, false>,
                         cudaFuncAttributeMaxDynamicSharedMemorySize, GEMM_SMEM);

    // Prep (detect + hist-zero + fp16 conversions), then CSR build
    prep_kernel<<<(PREP_TOTAL + 255) / 256, 256>>>(
        (const long long*)ei, x, w_l1, w_r1, w_l2, w_r2,
        x16, wl1, wr1, wl2, wr2, hist);
    hist_kernel<<<(N_EDGES + 255) / 256, 256>>>(ei, hist);
    scan1_kernel<<<SCAN_NB, 1024>>>(hist, off, bsum);
    scan2_kernel<<<1, 64>>>(bsum);
    scan3_kernel<<<(N_NODES + 255) / 256, 256>>>(off, bsum, cursor);
    fill_kernel<<<(N_EDGES + 255) / 256, 256>>>(ei, cursor, csr);

    const dim3 gemm_grid((N_NODES + 127) / 128, 2);
    const int agg_blocks = (N_NODES * 32 + 255) / 256;

    // Layer 1
    agg_kernel<D_IN><<<agg_blocks, 256>>>(x16, off, csr, a116);
    gemm1p_kernel<D_IN, true><<<gemm_grid, 256, GEMM_SMEM>>>(
        a116, x16, wl1, wr1, b_l1, nullptr, h16, N_NODES);

    // Layer 2
    agg_kernel<D_HID><<<agg_blocks, 256>>>(h16, off, csr, a216);
    gemm1p_kernel<D_HID, false><<<gemm_grid, 256, GEMM_SMEM>>>(
        a216, h16, wl2, wr2, b_l2, out, nullptr, N_NODES);
}